// round 7
// baseline (speedup 1.0000x reference)
#include <cuda_runtime.h>
#include <cuda_bf16.h>

// yolo_detect_target: out = sum_{i < cutoff} ( max(post_result[i,:]) + sum(boxes[i,:]) )
// cutoff = first row whose max-score < CONF (cumprod prefix-mask semantics).
//
// Single fused kernel:
//   - box warps  (1/16 of warps): sum(boxes) over ALL rows, pure coalesced stream
//   - score warps: 8-row/warp MLP=8 loop (proven 7.1 TB/s), row-max sum + cutoff
//   - last block (ticket pattern): exact fixup for rows >= cutoff + tail rows,
//     writes out[0], resets globals for the next graph replay.
// NOTE: assumes scores nonnegative (inputs uniform [0,1)) for 0-init int-bit max.

#define CONF_THRESH 0.25f

__device__ float        g_total  = 0.0f;
__device__ int          g_cutoff = 0x7fffffff;
__device__ unsigned int g_done   = 0u;

__device__ __forceinline__ float max4(float4 t) {
    return fmaxf(fmaxf(t.x, t.y), fmaxf(t.z, t.w));
}

__global__ void yolo_fused_kernel(const float4* __restrict__ pr4,
                                  const float4* __restrict__ bx4,
                                  int n, int c, float* __restrict__ out) {
    const int lane   = threadIdx.x & 31;
    const int gwarp  = (int)((blockIdx.x * blockDim.x + threadIdx.x) >> 5);
    const int nwarps = (int)((gridDim.x * blockDim.x) >> 5);
    const int nv     = c >> 2;          // 20 float4 per row
    const int ngrp   = n >> 3;          // 8-row groups
    const int nboxw  = nwarps >> 4;     // 1/16 of warps stream boxes

    float acc = 0.0f;

    if (gwarp < nboxw) {
        // Pure coalesced box stream over ALL rows.
        const int tid = gwarp * 32 + lane;
        const int nth = nboxw * 32;
        for (int i = tid; i < n; i += nth) {
            float4 bb = __ldcs(&bx4[i]);
            acc += (bb.x + bb.y) + (bb.z + bb.w);
        }
    } else {
        // Pure score stream: one warp per 8-row group, lanes 0..19 active,
        // 8 independent LDG.128 per lane before any reduction (MLP=8).
        const int sw  = gwarp - nboxw;
        const int nsw = nwarps - nboxw;
        for (int g = sw; g < ngrp; g += nsw) {
            const int row0 = g << 3;
            const long long b = (long long)row0 * nv;

            float m[8];
            #pragma unroll
            for (int k = 0; k < 8; k++) m[k] = 0.0f;

            if (lane < nv) {
                float4 t[8];
                #pragma unroll
                for (int k = 0; k < 8; k++)
                    t[k] = __ldcs(&pr4[b + (long long)k * nv + lane]);
                #pragma unroll
                for (int k = 0; k < 8; k++) m[k] = max4(t[k]);
            }

            int r[8];
            #pragma unroll
            for (int k = 0; k < 8; k++)  // nonneg floats: int-bit order == float order
                r[k] = __reduce_max_sync(0xffffffffu, __float_as_int(m[k]));

            if (lane < 8) acc += __int_as_float(r[lane]);

            if (lane == 0) {
                int bad = 8;
                #pragma unroll
                for (int k = 7; k >= 0; k--)
                    if (__int_as_float(r[k]) < CONF_THRESH) bad = k;
                if (bad < 8) atomicMin(&g_cutoff, row0 + bad);
            }
        }
    }

    // Block reduction -> one atomicAdd per block.
    __shared__ float sh[256];
    sh[threadIdx.x] = acc;
    __syncthreads();
    #pragma unroll
    for (int o = 128; o > 0; o >>= 1) {
        if (threadIdx.x < o) sh[threadIdx.x] += sh[threadIdx.x + o];
        __syncthreads();
    }

    __shared__ int s_last;
    if (threadIdx.x == 0) {
        atomicAdd(&g_total, sh[0]);
        __threadfence();  // make this block's total/cutoff visible before ticket
        unsigned int ticket = atomicAdd(&g_done, 1u);
        s_last = (ticket == gridDim.x - 1u) ? 1 : 0;
    }
    __syncthreads();
    if (!s_last) return;

    // ---- Last block only: fixup + output + reset ----
    const int warp  = threadIdx.x >> 5;     // 8 warps
    const int ngrp8 = (n >> 3) << 3;

    __shared__ int s_cut;
    if (threadIdx.x == 0)
        s_cut = min(atomicMin(&g_cutoff, 0x7fffffff), n);  // atomic read (bypass L1)
    __syncthreads();

    float adj = 0.0f;

    // Warp 0: tail rows [ngrp8, n) in order (may lower the cutoff).
    if (warp == 0) {
        int cut = s_cut;
        for (int row = ngrp8; row < n; row++) {
            if (row < cut) {
                float mm = 0.0f;
                for (int v = lane; v < nv; v += 32)
                    mm = fmaxf(mm, max4(pr4[(long long)row * nv + v]));
                float sc = __int_as_float(
                    __reduce_max_sync(0xffffffffu, __float_as_int(mm)));
                if (sc < CONF_THRESH) {
                    cut = row;                       // excluded: remove its boxsum
                    if (lane == 0) {
                        float4 bb = bx4[row];
                        adj -= (bb.x + bb.y) + (bb.z + bb.w);
                    }
                } else if (lane == 0) {
                    adj += sc;                       // boxsum already in g_total
                }
            } else if (lane == 0) {
                float4 bb = bx4[row];                // excluded tail row
                adj -= (bb.x + bb.y) + (bb.z + bb.w);
            }
        }
        if (lane == 0) s_cut = cut;
    }
    __syncthreads();
    const int cut = s_cut;

    // Subtract excluded group rows [cut, ngrp8): one row per warp, strided.
    for (int row = cut + warp; row < ngrp8; row += 8) {
        float mm = 0.0f;
        for (int v = lane; v < nv; v += 32)
            mm = fmaxf(mm, max4(pr4[(long long)row * nv + v]));
        float sc = __int_as_float(__reduce_max_sync(0xffffffffu, __float_as_int(mm)));
        if (lane == 0) {
            float4 bb = bx4[row];
            adj -= sc + ((bb.x + bb.y) + (bb.z + bb.w));
        }
    }

    sh[threadIdx.x] = adj;
    __syncthreads();
    #pragma unroll
    for (int o = 128; o > 0; o >>= 1) {
        if (threadIdx.x < o) sh[threadIdx.x] += sh[threadIdx.x + o];
        __syncthreads();
    }
    if (threadIdx.x == 0) {
        out[0] = atomicAdd(&g_total, 0.0f) + sh[0];
        g_total  = 0.0f;            // reset for next graph replay
        g_cutoff = 0x7fffffff;
        g_done   = 0u;
    }
}

extern "C" void kernel_launch(void* const* d_in, const int* in_sizes, int n_in,
                              void* d_out, int out_size) {
    const float* pr = (const float*)d_in[0];   // post_result [N, C] float32
    const float* bx = (const float*)d_in[1];   // pre_post_boxes [N, 4] float32
    const int nrows = in_sizes[1] / 4;
    const int c     = in_sizes[0] / nrows;     // 80

    yolo_fused_kernel<<<2368, 256>>>((const float4*)pr, (const float4*)bx,
                                     nrows, c, (float*)d_out);
}